// round 5
// baseline (speedup 1.0000x reference)
#include <cuda_runtime.h>

#define THREADS 256
#define NBATCH  32      // batches per block (8 threads per batch)

__global__ __launch_bounds__(THREADS, 2)
void gcn_fused(const float* __restrict__ x,
               const float* __restrict__ adj,
               const float* __restrict__ edg,
               const float* __restrict__ wb, const float* __restrict__ bb,
               const float* __restrict__ w1, const float* __restrict__ b1,
               const float* __restrict__ w2, const float* __restrict__ b2,
               const float* __restrict__ wg, const float* __restrict__ bg,
               const float* __restrict__ wf, const float* __restrict__ bf,
               float* __restrict__ out, int B)
{
    // ---- shared: weights (broadcast reads) + per-batch exchange tiles ----
    // All arrays read/written through float4 MUST be 16B aligned (shared float
    // arrays are otherwise only 4B aligned -> misaligned-address trap).
    __shared__ alignas(16) float F1S[NBATCH][160];  // 8x16 f1 tiles, row stride 20 (16B aligned)
    __shared__ alignas(16) float w1S[32 * 16];      // (NFEAT=32, NHID1=16)
    __shared__ alignas(16) float wbS[8 * 32];       // (INTER=8, NFEAT=32)
    __shared__ alignas(16) float w2S[16 * 8];       // (16, 8)
    __shared__ alignas(16) float wgS[8 * 8];        // (8, 8)
    __shared__ float T[NBATCH][72];                 // 8x8 tiles, row stride 9 (scalar only)
    __shared__ float bbS[8], b1S[16], b2S[8], bgS[8], wfS[16], bfS[2];

    const int tid = threadIdx.x;
    const int lb  = tid >> 3;            // local batch 0..31
    const int v   = tid & 7;             // node id 0..7
    const long long b = (long long)blockIdx.x * NBATCH + lb;
    const long long bc = (b < B) ? b : (long long)(B - 1);   // clamped for loads

    // ---- stage weights into shared ----
    wbS[tid] = wb[tid];
    w1S[tid] = w1[tid];
    w1S[256 + tid] = w1[256 + tid];
    if (tid < 128) w2S[tid] = w2[tid];
    if (tid < 64)  wgS[tid] = wg[tid];
    if (tid < 16) { b1S[tid] = b1[tid]; wfS[tid] = wf[tid]; }
    if (tid < 8)  { bbS[tid] = bb[tid]; b2S[tid] = b2[tid]; bgS[tid] = bg[tid]; }
    if (tid < 2)  bfS[tid] = bf[tid];
    __syncthreads();

    // ---- load this node's row of x: type + 32 feats (contiguous per lane) ----
    const float* xr = x + bc * 264 + v * 33;
    const float tv = xr[0];
    float feat[32];
    #pragma unroll
    for (int c = 0; c < 32; ++c) feat[c] = xr[1 + c];

    // ---- Fk column v: Fk[o][v] = bb[o] + sum_c feat[c]*wb[o][c] ----
    float fk[8];
    #pragma unroll
    for (int o = 0; o < 8; ++o) {
        const float4* w4 = reinterpret_cast<const float4*>(wbS + o * 32);
        float acc = bbS[o];
        #pragma unroll
        for (int q = 0; q < 8; ++q) {
            float4 w = w4[q];
            acc = fmaf(feat[4*q+0], w.x, acc);
            acc = fmaf(feat[4*q+1], w.y, acc);
            acc = fmaf(feat[4*q+2], w.z, acc);
            acc = fmaf(feat[4*q+3], w.w, acc);
        }
        fk[o] = acc;
    }
    float* Tb = T[lb];
    #pragma unroll
    for (int o = 0; o < 8; ++o) Tb[o * 9 + v] = fk[o];

    // ---- f1 row v: f1 = feat @ w1 (no bias yet; bias applied after W contraction) ----
    float f1[16];
    #pragma unroll
    for (int j = 0; j < 16; ++j) f1[j] = 0.f;
    #pragma unroll
    for (int c = 0; c < 32; ++c) {
        const float fc = feat[c];
        const float4* w4 = reinterpret_cast<const float4*>(w1S + c * 16);
        #pragma unroll
        for (int q = 0; q < 4; ++q) {
            float4 w = w4[q];
            f1[4*q+0] = fmaf(fc, w.x, f1[4*q+0]);
            f1[4*q+1] = fmaf(fc, w.y, f1[4*q+1]);
            f1[4*q+2] = fmaf(fc, w.z, f1[4*q+2]);
            f1[4*q+3] = fmaf(fc, w.w, f1[4*q+3]);
        }
    }
    {
        float4* fb = reinterpret_cast<float4*>(F1S[lb] + v * 20);
        fb[0] = make_float4(f1[0],  f1[1],  f1[2],  f1[3]);
        fb[1] = make_float4(f1[4],  f1[5],  f1[6],  f1[7]);
        fb[2] = make_float4(f1[8],  f1[9],  f1[10], f1[11]);
        fb[3] = make_float4(f1[12], f1[13], f1[14], f1[15]);
    }

    // issue adj/edge row loads now so their latency overlaps M/softmax
    const float4* a4 = reinterpret_cast<const float4*>(adj + bc * 64 + v * 8);
    const float4* e4 = reinterpret_cast<const float4*>(edg + bc * 64 + v * 8);
    float4 aLo = a4[0], aHi = a4[1];
    float4 eLo = e4[0], eHi = e4[1];

    __syncwarp();

    // ---- M column v: M[i][v] = sum_k Fk[i][k] * Fk[k][v]; softmax over i (local) ----
    float mcol[8];
    #pragma unroll
    for (int i = 0; i < 8; ++i) {
        float acc = 0.f;
        #pragma unroll
        for (int k = 0; k < 8; ++k) acc = fmaf(Tb[i * 9 + k], fk[k], acc);
        mcol[i] = acc;
    }
    float mx = mcol[0];
    #pragma unroll
    for (int i = 1; i < 8; ++i) mx = fmaxf(mx, mcol[i]);
    float ex[8], ssum = 0.f;
    #pragma unroll
    for (int i = 0; i < 8; ++i) { ex[i] = __expf(mcol[i] - mx); ssum += ex[i]; }
    const float inv = __fdividef(1.f, ssum);

    __syncwarp();   // all lanes done reading Fk from T before overwrite
    #pragma unroll
    for (int i = 0; i < 8; ++i) Tb[i * 9 + v] = ex[i] * inv;   // S column
    __syncwarp();

    // ---- W row v: W[v][w] = adj[v][w] * (S[v][w] + edge[v][w]) ----
    float Wr[8];
    Wr[0] = aLo.x * (Tb[v*9+0] + eLo.x);
    Wr[1] = aLo.y * (Tb[v*9+1] + eLo.y);
    Wr[2] = aLo.z * (Tb[v*9+2] + eLo.z);
    Wr[3] = aLo.w * (Tb[v*9+3] + eLo.w);
    Wr[4] = aHi.x * (Tb[v*9+4] + eHi.x);
    Wr[5] = aHi.y * (Tb[v*9+5] + eHi.y);
    Wr[6] = aHi.z * (Tb[v*9+6] + eHi.z);
    Wr[7] = aHi.w * (Tb[v*9+7] + eHi.w);

    // ---- h1 row v: lrelu(b1 + sum_w W[v][w] * f1[w][:]) ----
    float h1[16];
    #pragma unroll
    for (int j = 0; j < 16; ++j) h1[j] = b1S[j];
    #pragma unroll
    for (int w = 0; w < 8; ++w) {
        const float ww = Wr[w];
        const float4* f4 = reinterpret_cast<const float4*>(F1S[lb] + w * 20);
        #pragma unroll
        for (int q = 0; q < 4; ++q) {
            float4 fv = f4[q];
            h1[4*q+0] = fmaf(ww, fv.x, h1[4*q+0]);
            h1[4*q+1] = fmaf(ww, fv.y, h1[4*q+1]);
            h1[4*q+2] = fmaf(ww, fv.z, h1[4*q+2]);
            h1[4*q+3] = fmaf(ww, fv.w, h1[4*q+3]);
        }
    }
    #pragma unroll
    for (int j = 0; j < 16; ++j) h1[j] = (h1[j] > 0.f) ? h1[j] : 0.01f * h1[j];

    // ---- g2 row v = h1 @ w2 ----
    float g2[8];
    #pragma unroll
    for (int o = 0; o < 8; ++o) g2[o] = 0.f;
    #pragma unroll
    for (int j = 0; j < 16; ++j) {
        const float hj = h1[j];
        const float4* w4 = reinterpret_cast<const float4*>(w2S + j * 8);
        float4 wl = w4[0], wh = w4[1];
        g2[0] = fmaf(hj, wl.x, g2[0]); g2[1] = fmaf(hj, wl.y, g2[1]);
        g2[2] = fmaf(hj, wl.z, g2[2]); g2[3] = fmaf(hj, wl.w, g2[3]);
        g2[4] = fmaf(hj, wh.x, g2[4]); g2[5] = fmaf(hj, wh.y, g2[5]);
        g2[6] = fmaf(hj, wh.z, g2[6]); g2[7] = fmaf(hj, wh.w, g2[7]);
    }
    __syncwarp();   // all lanes done reading S rows from T
    #pragma unroll
    for (int o = 0; o < 8; ++o) Tb[v * 9 + o] = g2[o];
    __syncwarp();

    // ---- h2 row v: lrelu(b2 + sum_w W[v][w] * g2[w][:]) ----
    float h2[8];
    #pragma unroll
    for (int o = 0; o < 8; ++o) h2[o] = b2S[o];
    #pragma unroll
    for (int w = 0; w < 8; ++w) {
        const float ww = Wr[w];
        #pragma unroll
        for (int o = 0; o < 8; ++o) h2[o] = fmaf(ww, Tb[w * 9 + o], h2[o]);
    }
    #pragma unroll
    for (int o = 0; o < 8; ++o) h2[o] = (h2[o] > 0.f) ? h2[o] : 0.01f * h2[o];

    // ---- attention pooling per type, softmax over nodes via 8-lane butterflies ----
    float xp[8];
    #pragma unroll
    for (int o = 0; o < 8; ++o) xp[o] = 0.f;
    #pragma unroll
    for (int t = 0; t < 2; ++t) {
        const float maskv = (tv == (float)t) ? 1.f : 0.f;
        float hm[8];
        #pragma unroll
        for (int o = 0; o < 8; ++o) hm[o] = h2[o] * maskv;
        #pragma unroll
        for (int o = 0; o < 8; ++o) {
            const float4* w4 = reinterpret_cast<const float4*>(wgS + o * 8);
            float4 wl = w4[0], wh = w4[1];
            float lg = bgS[o];
            lg = fmaf(hm[0], wl.x, lg); lg = fmaf(hm[1], wl.y, lg);
            lg = fmaf(hm[2], wl.z, lg); lg = fmaf(hm[3], wl.w, lg);
            lg = fmaf(hm[4], wh.x, lg); lg = fmaf(hm[5], wh.y, lg);
            lg = fmaf(hm[6], wh.z, lg); lg = fmaf(hm[7], wh.w, lg);
            // softmax over the 8 nodes (lanes of this group)
            float mv = lg;
            mv = fmaxf(mv, __shfl_xor_sync(0xffffffffu, mv, 1));
            mv = fmaxf(mv, __shfl_xor_sync(0xffffffffu, mv, 2));
            mv = fmaxf(mv, __shfl_xor_sync(0xffffffffu, mv, 4));
            float ev = __expf(lg - mv);
            float sv = ev;
            sv += __shfl_xor_sync(0xffffffffu, sv, 1);
            sv += __shfl_xor_sync(0xffffffffu, sv, 2);
            sv += __shfl_xor_sync(0xffffffffu, sv, 4);
            float pv = ev * hm[o];
            pv += __shfl_xor_sync(0xffffffffu, pv, 1);
            pv += __shfl_xor_sync(0xffffffffu, pv, 2);
            pv += __shfl_xor_sync(0xffffffffu, pv, 4);
            xp[o] += 0.5f * __fdividef(pv, sv);   // mean over the 2 types folded in
        }
    }

    // ---- classifier head; lane 0 of each group stores 2 floats ----
    if (v == 0 && b < B) {
        float o0 = bfS[0], o1 = bfS[1];
        #pragma unroll
        for (int o = 0; o < 8; ++o) {
            o0 = fmaf(xp[o], wfS[o],     o0);
            o1 = fmaf(xp[o], wfS[8 + o], o1);
        }
        reinterpret_cast<float2*>(out)[b] = make_float2(o0, o1);
    }
}

extern "C" void kernel_launch(void* const* d_in, const int* in_sizes, int n_in,
                              void* d_out, int out_size)
{
    const float* x   = (const float*)d_in[0];
    const float* adj = (const float*)d_in[1];
    const float* edg = (const float*)d_in[2];
    // d_in[3]=wa, d_in[4]=ba are unused by the reference
    const float* wb  = (const float*)d_in[5];
    const float* bb  = (const float*)d_in[6];
    const float* w1  = (const float*)d_in[7];
    const float* b1  = (const float*)d_in[8];
    const float* w2  = (const float*)d_in[9];
    const float* b2  = (const float*)d_in[10];
    const float* wg  = (const float*)d_in[11];
    const float* bg  = (const float*)d_in[12];
    const float* wf  = (const float*)d_in[13];
    const float* bf  = (const float*)d_in[14];
    float* out = (float*)d_out;

    const int B = in_sizes[0] / 264;            // 8 nodes * 33 channels
    const int grid = (B + NBATCH - 1) / NBATCH;
    gcn_fused<<<grid, THREADS>>>(x, adj, edg, wb, bb, w1, b1, w2, b2,
                                 wg, bg, wf, bf, out, B);
}

// round 7
// speedup vs baseline: 1.1768x; 1.1768x over previous
#include <cuda_runtime.h>

#define THREADS 256
#define NBATCH  32      // batches per block (8 threads per batch)

__global__ __launch_bounds__(THREADS, 3)
void gcn_fused(const float* __restrict__ x,
               const float* __restrict__ adj,
               const float* __restrict__ edg,
               const float* __restrict__ wb, const float* __restrict__ bb,
               const float* __restrict__ w1, const float* __restrict__ b1,
               const float* __restrict__ w2, const float* __restrict__ b2,
               const float* __restrict__ wg, const float* __restrict__ bg,
               const float* __restrict__ wf, const float* __restrict__ bf,
               float* __restrict__ out, int B)
{
    // S1: per-batch 264-float x rows (staged coalesced), later ALIASED as the
    // 8x16 f1 tile (row stride 20 floats, 16B aligned). 264*4=1056B row pitch.
    __shared__ alignas(16) float S1[NBATCH][264];
    __shared__ alignas(16) float w1S[32 * 16];      // (NFEAT=32, NHID1=16) row-major
    __shared__ alignas(16) float wbT[32 * 8];       // wb transposed: [c][o]
    __shared__ alignas(16) float w2S[16 * 8];
    __shared__ alignas(16) float wgS[8 * 8];
    __shared__ float T[NBATCH][72];                 // 8x8 tiles, row stride 9 (scalar)
    __shared__ float bbS[8], b1S[16], b2S[8], bgS[8], wfS[16], bfS[2];

    const int tid = threadIdx.x;
    const int lb  = tid >> 3;            // local batch 0..31
    const int v   = tid & 7;             // node id 0..7
    const long long b = (long long)blockIdx.x * NBATCH + lb;
    const long long bc = (b < B) ? b : (long long)(B - 1);

    // ---- stage weights into shared ----
    wbT[tid] = wb[(tid & 7) * 32 + (tid >> 3)];     // wbT[c*8+o] = wb[o*32+c]
    w1S[tid] = w1[tid];
    w1S[256 + tid] = w1[256 + tid];
    if (tid < 128) w2S[tid] = w2[tid];
    if (tid < 64)  wgS[tid] = wg[tid];
    if (tid < 16) { b1S[tid] = b1[tid]; wfS[tid] = wf[tid]; }
    if (tid < 8)  { bbS[tid] = bb[tid]; b2S[tid] = b2[tid]; bgS[tid] = bg[tid]; }
    if (tid < 2)  bfS[tid] = bf[tid];

    // ---- stage x coalesced: 32 batches * 264 floats = 2112 float4 ----
    {
        const float4* xg = reinterpret_cast<const float4*>(x)
                         + (size_t)blockIdx.x * (NBATCH * 66);
        float4* xs4 = reinterpret_cast<float4*>(&S1[0][0]);
        #pragma unroll
        for (int i = 0; i < 8; ++i) xs4[tid + 256 * i] = xg[tid + 256 * i];
        if (tid < 64) xs4[2048 + tid] = xg[2048 + tid];
    }
    __syncthreads();

    const float* xrow = S1[lb] + v * 33;   // this node's [type | 32 feats]
    const float tv = xrow[0];

    // ---- merged Fk + f1 pass over feature channels (feat read from shared) ----
    // Fk[o][v] = bb[o] + sum_c feat[c]*wb[o][c]   (8 accumulators)
    // f1[v][:] = sum_c feat[c]*w1[c][:]           (16 accumulators)
    float fk[8];
    #pragma unroll
    for (int o = 0; o < 8; ++o) fk[o] = bbS[o];
    float f1[16];
    #pragma unroll
    for (int j = 0; j < 16; ++j) f1[j] = 0.f;

    #pragma unroll
    for (int c = 0; c < 32; ++c) {
        const float fc = xrow[1 + c];
        const float4* wt4 = reinterpret_cast<const float4*>(wbT + c * 8);
        float4 tl = wt4[0], th = wt4[1];
        fk[0] = fmaf(fc, tl.x, fk[0]); fk[1] = fmaf(fc, tl.y, fk[1]);
        fk[2] = fmaf(fc, tl.z, fk[2]); fk[3] = fmaf(fc, tl.w, fk[3]);
        fk[4] = fmaf(fc, th.x, fk[4]); fk[5] = fmaf(fc, th.y, fk[5]);
        fk[6] = fmaf(fc, th.z, fk[6]); fk[7] = fmaf(fc, th.w, fk[7]);
        const float4* w4 = reinterpret_cast<const float4*>(w1S + c * 16);
        #pragma unroll
        for (int q = 0; q < 4; ++q) {
            float4 w = w4[q];
            f1[4*q+0] = fmaf(fc, w.x, f1[4*q+0]);
            f1[4*q+1] = fmaf(fc, w.y, f1[4*q+1]);
            f1[4*q+2] = fmaf(fc, w.z, f1[4*q+2]);
            f1[4*q+3] = fmaf(fc, w.w, f1[4*q+3]);
        }
    }

    float* Tb = T[lb];
    #pragma unroll
    for (int o = 0; o < 8; ++o) Tb[o * 9 + v] = fk[o];

    // all lanes of this group are done reading x from S1 -> safe to alias with f1
    __syncwarp();
    {
        float4* fb = reinterpret_cast<float4*>(S1[lb] + v * 20);
        fb[0] = make_float4(f1[0],  f1[1],  f1[2],  f1[3]);
        fb[1] = make_float4(f1[4],  f1[5],  f1[6],  f1[7]);
        fb[2] = make_float4(f1[8],  f1[9],  f1[10], f1[11]);
        fb[3] = make_float4(f1[12], f1[13], f1[14], f1[15]);
    }

    // issue adj/edge row loads now so DRAM latency overlaps M/softmax
    const float4* a4 = reinterpret_cast<const float4*>(adj + bc * 64 + v * 8);
    const float4* e4 = reinterpret_cast<const float4*>(edg + bc * 64 + v * 8);
    float4 aLo = a4[0], aHi = a4[1];
    float4 eLo = e4[0], eHi = e4[1];

    __syncwarp();

    // ---- M column v: M[i][v] = sum_k Fk[i][k]*Fk[k][v]; softmax over i ----
    float mcol[8];
    #pragma unroll
    for (int i = 0; i < 8; ++i) {
        float acc = 0.f;
        #pragma unroll
        for (int k = 0; k < 8; ++k) acc = fmaf(Tb[i * 9 + k], fk[k], acc);
        mcol[i] = acc;
    }
    float mx = mcol[0];
    #pragma unroll
    for (int i = 1; i < 8; ++i) mx = fmaxf(mx, mcol[i]);
    float ex[8], ssum = 0.f;
    #pragma unroll
    for (int i = 0; i < 8; ++i) { ex[i] = __expf(mcol[i] - mx); ssum += ex[i]; }
    const float inv = __fdividef(1.f, ssum);

    __syncwarp();   // all lanes done reading Fk from T before overwrite
    #pragma unroll
    for (int i = 0; i < 8; ++i) Tb[i * 9 + v] = ex[i] * inv;   // S column
    __syncwarp();

    // ---- W row v = adj * (S + edge) ----
    float Wr[8];
    Wr[0] = aLo.x * (Tb[v*9+0] + eLo.x);
    Wr[1] = aLo.y * (Tb[v*9+1] + eLo.y);
    Wr[2] = aLo.z * (Tb[v*9+2] + eLo.z);
    Wr[3] = aLo.w * (Tb[v*9+3] + eLo.w);
    Wr[4] = aHi.x * (Tb[v*9+4] + eHi.x);
    Wr[5] = aHi.y * (Tb[v*9+5] + eHi.y);
    Wr[6] = aHi.z * (Tb[v*9+6] + eHi.z);
    Wr[7] = aHi.w * (Tb[v*9+7] + eHi.w);

    // ---- h1 row v = lrelu(b1 + sum_w W[v][w] * f1[w][:]) ----
    float h1[16];
    #pragma unroll
    for (int j = 0; j < 16; ++j) h1[j] = b1S[j];
    #pragma unroll
    for (int w = 0; w < 8; ++w) {
        const float ww = Wr[w];
        const float4* f4 = reinterpret_cast<const float4*>(S1[lb] + w * 20);
        #pragma unroll
        for (int q = 0; q < 4; ++q) {
            float4 fv = f4[q];
            h1[4*q+0] = fmaf(ww, fv.x, h1[4*q+0]);
            h1[4*q+1] = fmaf(ww, fv.y, h1[4*q+1]);
            h1[4*q+2] = fmaf(ww, fv.z, h1[4*q+2]);
            h1[4*q+3] = fmaf(ww, fv.w, h1[4*q+3]);
        }
    }
    #pragma unroll
    for (int j = 0; j < 16; ++j) h1[j] = (h1[j] > 0.f) ? h1[j] : 0.01f * h1[j];

    // ---- g2 row v = h1 @ w2 ----
    float g2[8];
    #pragma unroll
    for (int o = 0; o < 8; ++o) g2[o] = 0.f;
    #pragma unroll
    for (int j = 0; j < 16; ++j) {
        const float hj = h1[j];
        const float4* w4 = reinterpret_cast<const float4*>(w2S + j * 8);
        float4 wl = w4[0], wh = w4[1];
        g2[0] = fmaf(hj, wl.x, g2[0]); g2[1] = fmaf(hj, wl.y, g2[1]);
        g2[2] = fmaf(hj, wl.z, g2[2]); g2[3] = fmaf(hj, wl.w, g2[3]);
        g2[4] = fmaf(hj, wh.x, g2[4]); g2[5] = fmaf(hj, wh.y, g2[5]);
        g2[6] = fmaf(hj, wh.z, g2[6]); g2[7] = fmaf(hj, wh.w, g2[7]);
    }
    __syncwarp();   // all lanes done reading S rows from T
    #pragma unroll
    for (int o = 0; o < 8; ++o) Tb[v * 9 + o] = g2[o];
    __syncwarp();

    // ---- h2 row v = lrelu(b2 + sum_w W[v][w] * g2[w][:]) ----
    float h2[8];
    #pragma unroll
    for (int o = 0; o < 8; ++o) h2[o] = b2S[o];
    #pragma unroll
    for (int w = 0; w < 8; ++w) {
        const float ww = Wr[w];
        #pragma unroll
        for (int o = 0; o < 8; ++o) h2[o] = fmaf(ww, Tb[w * 9 + o], h2[o]);
    }
    #pragma unroll
    for (int o = 0; o < 8; ++o) h2[o] = (h2[o] > 0.f) ? h2[o] : 0.01f * h2[o];

    // ---- attention pooling per type; softmax over 8 nodes via shuffles ----
    float xp[8];
    #pragma unroll
    for (int o = 0; o < 8; ++o) xp[o] = 0.f;
    #pragma unroll
    for (int t = 0; t < 2; ++t) {
        const float maskv = (tv == (float)t) ? 1.f : 0.f;
        float hm[8];
        #pragma unroll
        for (int o = 0; o < 8; ++o) hm[o] = h2[o] * maskv;
        #pragma unroll
        for (int o = 0; o < 8; ++o) {
            const float4* w4 = reinterpret_cast<const float4*>(wgS + o * 8);
            float4 wl = w4[0], wh = w4[1];
            float lg = bgS[o];
            lg = fmaf(hm[0], wl.x, lg); lg = fmaf(hm[1], wl.y, lg);
            lg = fmaf(hm[2], wl.z, lg); lg = fmaf(hm[3], wl.w, lg);
            lg = fmaf(hm[4], wh.x, lg); lg = fmaf(hm[5], wh.y, lg);
            lg = fmaf(hm[6], wh.z, lg); lg = fmaf(hm[7], wh.w, lg);
            float mv = lg;
            mv = fmaxf(mv, __shfl_xor_sync(0xffffffffu, mv, 1));
            mv = fmaxf(mv, __shfl_xor_sync(0xffffffffu, mv, 2));
            mv = fmaxf(mv, __shfl_xor_sync(0xffffffffu, mv, 4));
            float ev = __expf(lg - mv);
            float sv = ev;
            sv += __shfl_xor_sync(0xffffffffu, sv, 1);
            sv += __shfl_xor_sync(0xffffffffu, sv, 2);
            sv += __shfl_xor_sync(0xffffffffu, sv, 4);
            float pv = ev * hm[o];
            pv += __shfl_xor_sync(0xffffffffu, pv, 1);
            pv += __shfl_xor_sync(0xffffffffu, pv, 2);
            pv += __shfl_xor_sync(0xffffffffu, pv, 4);
            xp[o] += 0.5f * __fdividef(pv, sv);
        }
    }

    // ---- classifier head; lane 0 of each group stores 2 floats ----
    if (v == 0 && b < B) {
        float o0 = bfS[0], o1 = bfS[1];
        #pragma unroll
        for (int o = 0; o < 8; ++o) {
            o0 = fmaf(xp[o], wfS[o],     o0);
            o1 = fmaf(xp[o], wfS[8 + o], o1);
        }
        reinterpret_cast<float2*>(out)[b] = make_float2(o0, o1);
    }
}

extern "C" void kernel_launch(void* const* d_in, const int* in_sizes, int n_in,
                              void* d_out, int out_size)
{
    const float* x   = (const float*)d_in[0];
    const float* adj = (const float*)d_in[1];
    const float* edg = (const float*)d_in[2];
    // d_in[3]=wa, d_in[4]=ba unused by the reference
    const float* wb  = (const float*)d_in[5];
    const float* bb  = (const float*)d_in[6];
    const float* w1  = (const float*)d_in[7];
    const float* b1  = (const float*)d_in[8];
    const float* w2  = (const float*)d_in[9];
    const float* b2  = (const float*)d_in[10];
    const float* wg  = (const float*)d_in[11];
    const float* bg  = (const float*)d_in[12];
    const float* wf  = (const float*)d_in[13];
    const float* bf  = (const float*)d_in[14];
    float* out = (float*)d_out;

    const int B = in_sizes[0] / 264;
    const int grid = (B + NBATCH - 1) / NBATCH;
    gcn_fused<<<grid, THREADS>>>(x, adj, edg, wb, bb, w1, b1, w2, b2,
                                 wg, bg, wf, bf, out, B);
}